// round 15
// baseline (speedup 1.0000x reference)
#include <cuda_runtime.h>
#include <cuda_fp16.h>
#include <math.h>

#define D_IN  256
#define D_OUT 64
#define NH    4
#define NMAX  100000
#define EMAX  3200000
#define P_TOT 5
#define SCAN_CHUNK 1024
#define SCAN_BLOCKS 98   // ceil(100000/1024)

// ---------------- scratch (device globals; no allocations allowed) ----------
__device__ uint4 g_hh4[(size_t)2 * NMAX * 32];                     // fp16 h, head-interleaved
__device__ __align__(16) float4 g_a0p[P_TOT * NMAX];               // a0 packed over 4 heads
__device__ __align__(16) float4 g_a1p[P_TOT * NMAX];               // a1 packed over 4 heads
__device__ __align__(16) float g_acc[(size_t)8 * NMAX * D_OUT];    // acc[mi][n][64]
__device__ int   g_cnt[P_TOT * NMAX];                              // per-row edge counts
__device__ int   g_rowptr[P_TOT * (NMAX + 1)];                     // CSR row pointers
__device__ int   g_cursor[P_TOT * NMAX];                           // scatter cursors
__device__ int   g_part[P_TOT * (SCAN_BLOCKS + 1)];                // scan partials
__device__ __align__(8) int2 g_cedge[(size_t)P_TOT * EMAX];        // CSR (col, val-bits)

// ---------------- 1) GEMM, 4-n register blocking ----------------------------
// thread t: dim-slice ds=(t>>6)*16, n-columns {nl, nl+64, nl+128, nl+192}.
// Per kk: 4 broadcast LDS.128 (W slice) reused across 4 n -> LDS:FFMA2 = 1:8.
__global__ void gemm_kernel(const float* __restrict__ x, const float* __restrict__ W,
                            const float* __restrict__ att0, const float* __restrict__ att1,
                            int N) {
    __shared__ __align__(16) float Ws[64][68];
    __shared__ float att_s[3][2][64];
    __shared__ float red[4][264];         // cross-slice att reduction
    int mi  = blockIdx.x;                 // mi fast: consecutive blocks share x slice
    int m   = mi >> 2, i = mi & 3;
    int tid = threadIdx.x;
    int slice = tid >> 6, nl = tid & 63;
    int ds  = slice * 16;
    int nbase = blockIdx.y * 256;
    const float* Wb = W + (size_t)mi * D_OUT * D_IN;

    int pb = m ? 2 : 0, pc = m ? 3 : 2;
    for (int idx = tid; idx < pc * 2 * 64; idx += 256) {
        int k = idx / 128, rest = idx & 127;
        int which = rest >> 6, d = rest & 63;
        int p = pb + k;
        const float* src = which ? att1 : att0;
        att_s[k][which][d] = src[(p * NH + i) * 64 + d];
    }

    int nj[4], nc[4];
#pragma unroll
    for (int j = 0; j < 4; j++) {
        nj[j] = nbase + nl + 64 * j;
        nc[j] = nj[j] < N ? nj[j] : N - 1;   // clamp for loads
    }

    unsigned long long acc2[4][8];
#pragma unroll
    for (int j = 0; j < 4; j++)
#pragma unroll
        for (int q = 0; q < 8; q++) acc2[j][q] = 0ULL;

    for (int kc = 0; kc < 4; kc++) {
        __syncthreads();
        for (int idx = tid; idx < 4096; idx += 256) {
            int kk = idx & 63, d = idx >> 6;
            Ws[kk][d] = Wb[d * 256 + kc * 64 + kk];
        }
        __syncthreads();
        const float* xk = x + (size_t)(kc * 64) * N;
        for (int kk4 = 0; kk4 < 16; kk4++) {
            float xv[4][4];                       // [u][j], MLP=16
#pragma unroll
            for (int u = 0; u < 4; u++)
#pragma unroll
                for (int j = 0; j < 4; j++)
                    xv[u][j] = xk[(size_t)(kk4 * 4 + u) * N + nc[j]];
#pragma unroll
            for (int u = 0; u < 4; u++) {
                int kk = kk4 * 4 + u;
                const unsigned long long* wr = (const unsigned long long*)&Ws[kk][ds];
                unsigned long long w[8];
#pragma unroll
                for (int q = 0; q < 8; q += 2) {  // 4 x LDS.128
                    ulonglong2 t2 = ((const ulonglong2*)wr)[q >> 1];
                    w[q] = t2.x; w[q + 1] = t2.y;
                }
#pragma unroll
                for (int j = 0; j < 4; j++) {
                    unsigned long long xv2;
                    asm("mov.b64 %0, {%1, %1};" : "=l"(xv2) : "f"(xv[u][j]));
#pragma unroll
                    for (int q = 0; q < 8; q++)
                        asm("fma.rn.f32x2 %0, %1, %2, %0;" : "+l"(acc2[j][q]) : "l"(w[q]), "l"(xv2));
                }
            }
        }
    }

    // unpack: a[j][16]
    float a[4][16];
#pragma unroll
    for (int j = 0; j < 4; j++)
#pragma unroll
        for (int q = 0; q < 8; q++)
            asm("mov.b64 {%0, %1}, %2;" : "=f"(a[j][2 * q]), "=f"(a[j][2 * q + 1]) : "l"(acc2[j][q]));

    // fp16 h store: per n, 16 dims = 2 uint4 at slot i*8 + ds/8
#pragma unroll
    for (int j = 0; j < 4; j++) {
        if (nj[j] < N) {
            uint4* hq = &g_hh4[((size_t)m * NMAX + nj[j]) * 32 + i * 8 + (ds >> 3)];
            __half2 h0 = __floats2half2_rn(a[j][0],  a[j][1]);
            __half2 h1 = __floats2half2_rn(a[j][2],  a[j][3]);
            __half2 h2 = __floats2half2_rn(a[j][4],  a[j][5]);
            __half2 h3 = __floats2half2_rn(a[j][6],  a[j][7]);
            uint4 u0;
            u0.x = *(unsigned*)&h0; u0.y = *(unsigned*)&h1;
            u0.z = *(unsigned*)&h2; u0.w = *(unsigned*)&h3;
            h0 = __floats2half2_rn(a[j][8],  a[j][9]);
            h1 = __floats2half2_rn(a[j][10], a[j][11]);
            h2 = __floats2half2_rn(a[j][12], a[j][13]);
            h3 = __floats2half2_rn(a[j][14], a[j][15]);
            uint4 u1;
            u1.x = *(unsigned*)&h0; u1.y = *(unsigned*)&h1;
            u1.z = *(unsigned*)&h2; u1.w = *(unsigned*)&h3;
            hq[0] = u0; hq[1] = u1;
        }
    }

    // att scores: 16-dim partials + cross-slice smem reduction (fp32 exact)
    for (int k = 0; k < pc; k++) {
        for (int which = 0; which < 2; which++) {
            float part[4];
#pragma unroll
            for (int j = 0; j < 4; j++) {
                float s = 0.f;
#pragma unroll
                for (int d = 0; d < 16; d++)
                    s += a[j][d] * att_s[k][which][ds + d];
                part[j] = s;
            }
            __syncthreads();
#pragma unroll
            for (int j = 0; j < 4; j++)
                red[slice][nl + 64 * j] = part[j];
            __syncthreads();
            if (slice == 0) {
                int p = pb + k;
#pragma unroll
                for (int j = 0; j < 4; j++) {
                    int n_loc = nl + 64 * j;
                    int n = nbase + n_loc;
                    if (n < N) {
                        float s = red[0][n_loc] + red[1][n_loc] + red[2][n_loc] + red[3][n_loc];
                        float* dst = which ? (float*)&g_a1p[(size_t)p * NMAX + n]
                                           : (float*)&g_a0p[(size_t)p * NMAX + n];
                        dst[i] = s;
                    }
                }
            }
        }
    }
}

// ---------------- 2) CSR build ---------------------------------------------
__global__ void zero_cnt_kernel(int N) {
    int n = blockIdx.x * 256 + threadIdx.x;
    int p = blockIdx.y;
    if (n < N) g_cnt[p * NMAX + n] = 0;
}

__global__ void hist_kernel(const int* __restrict__ rows, int N, int E) {
    int e = blockIdx.x * 256 + threadIdx.x;
    int p = blockIdx.y;
    if (e >= E) return;
    int r = rows[(size_t)p * E + e];
    atomicAdd(&g_cnt[p * NMAX + r], 1);
}

// scan stage A: per-chunk totals
__global__ void scanA_kernel(int N) {
    __shared__ int wsum[32];
    int p = blockIdx.y, b = blockIdx.x, tid = threadIdx.x;
    int lane = tid & 31, wid = tid >> 5;
    int idx = b * SCAN_CHUNK + tid;
    int v = (idx < N) ? g_cnt[p * NMAX + idx] : 0;
#pragma unroll
    for (int s = 16; s; s >>= 1) v += __shfl_xor_sync(0xffffffffu, v, s);
    if (lane == 0) wsum[wid] = v;
    __syncthreads();
    if (wid == 0) {
        int t = wsum[lane];
#pragma unroll
        for (int s = 16; s; s >>= 1) t += __shfl_xor_sync(0xffffffffu, t, s);
        if (lane == 0) g_part[p * (SCAN_BLOCKS + 1) + b] = t;
    }
}

// scan stage B: exclusive scan of SCAN_BLOCKS partials per p; writes rowptr[N]
__global__ void scanB_kernel(int N) {
    __shared__ int s[128];
    int p = blockIdx.x, tid = threadIdx.x;
    int v = (tid < SCAN_BLOCKS) ? g_part[p * (SCAN_BLOCKS + 1) + tid] : 0;
    s[tid] = v;
    __syncthreads();
    for (int d = 1; d < 128; d <<= 1) {
        int t = (tid >= d) ? s[tid - d] : 0;
        __syncthreads();
        s[tid] += t;
        __syncthreads();
    }
    if (tid < SCAN_BLOCKS) g_part[p * (SCAN_BLOCKS + 1) + tid] = s[tid] - v;
    if (tid == SCAN_BLOCKS - 1) g_rowptr[p * (NMAX + 1) + N] = s[tid];
}

// scan stage C: local exclusive scan + block offset -> rowptr & cursor
__global__ void scanC_kernel(int N) {
    __shared__ int wsum[32];
    int p = blockIdx.y, b = blockIdx.x, tid = threadIdx.x;
    int lane = tid & 31, wid = tid >> 5;
    int idx = b * SCAN_CHUNK + tid;
    int v = (idx < N) ? g_cnt[p * NMAX + idx] : 0;
    int s = v;
#pragma unroll
    for (int d = 1; d < 32; d <<= 1) {
        int t = __shfl_up_sync(0xffffffffu, s, d);
        if (lane >= d) s += t;
    }
    if (lane == 31) wsum[wid] = s;
    __syncthreads();
    if (wid == 0) {
        int ws = wsum[lane];
#pragma unroll
        for (int d = 1; d < 32; d <<= 1) {
            int t = __shfl_up_sync(0xffffffffu, ws, d);
            if (lane >= d) ws += t;
        }
        wsum[lane] = ws;
    }
    __syncthreads();
    int prev = wid ? wsum[wid - 1] : 0;
    int excl = g_part[p * (SCAN_BLOCKS + 1) + b] + prev + s - v;
    if (idx < N) {
        g_rowptr[p * (NMAX + 1) + idx] = excl;
        g_cursor[p * NMAX + idx] = excl;
    }
}

__global__ void scatter_kernel(const int* __restrict__ rows, const int* __restrict__ cols,
                               const float* __restrict__ vals, int N, int E) {
    int e = blockIdx.x * 256 + threadIdx.x;
    int p = blockIdx.y;
    if (e >= E) return;
    size_t be = (size_t)p * E + e;
    int r = rows[be];
    int pos = atomicAdd(&g_cursor[p * NMAX + r], 1);
    g_cedge[(size_t)p * EMAX + pos] = make_int2(cols[be], __float_as_int(vals[be]));
}

// ---------------- 3) fused row aggregation: smem-staged edges, LDG.128 gather
__global__ void row_agg_kernel(int N) {
    __shared__ int   s_c[8][32];
    __shared__ float s_e[8][4][33];
    int lane = threadIdx.x & 31, w = threadIdx.x >> 5;
    int r = blockIdx.x * 8 + w;
    if (r >= N) return;
    int m = blockIdx.y;
    int hsel = lane >> 3;
    const uint4* hb = g_hh4 + (size_t)m * NMAX * 32;

    float accT[8];
#pragma unroll
    for (int q = 0; q < 8; q++) accT[q] = 0.f;

    int pb = m ? 2 : 0, pc = m ? 3 : 2;
    for (int k = 0; k < pc; k++) {
        int p = pb + k;
        const float4* a0 = g_a0p + (size_t)p * NMAX;
        float4 a1r = g_a1p[(size_t)p * NMAX + r];
        int start = g_rowptr[p * (NMAX + 1) + r];
        int end   = g_rowptr[p * (NMAX + 1) + r + 1];
        const int2* ced = g_cedge + (size_t)p * EMAX;

        float accP[8];
#pragma unroll
        for (int q = 0; q < 8; q++) accP[q] = 0.f;
        float4 den = make_float4(0.f, 0.f, 0.f, 0.f);

        for (int base = start; base < end; base += 32) {
            int e = base + lane;
            float e0 = 0.f, e1 = 0.f, e2 = 0.f, e3 = 0.f;
            int c = 0;
            if (e < end) {
                int2 ed = ced[e];
                c = ed.x;
                float v = __int_as_float(ed.y);
                float4 a0v = a0[c];
                e0 = __expf(v * (a0v.x + a1r.x));
                e1 = __expf(v * (a0v.y + a1r.y));
                e2 = __expf(v * (a0v.z + a1r.z));
                e3 = __expf(v * (a0v.w + a1r.w));
            }
            den.x += e0; den.y += e1; den.z += e2; den.w += e3;
            s_c[w][lane] = c;
            s_e[w][0][lane] = e0; s_e[w][1][lane] = e1;
            s_e[w][2][lane] = e2; s_e[w][3][lane] = e3;
            __syncwarp();
            int cnt = min(32, end - base);
#pragma unroll 4
            for (int j = 0; j < cnt; j++) {
                int   cj = s_c[w][j];
                float wg = s_e[w][hsel][j];
                uint4 hv = hb[(size_t)cj * 32 + lane];
                float2 f0 = __half22float2(*(__half2*)&hv.x);
                float2 f1 = __half22float2(*(__half2*)&hv.y);
                float2 f2 = __half22float2(*(__half2*)&hv.z);
                float2 f3 = __half22float2(*(__half2*)&hv.w);
                accP[0] += wg * f0.x; accP[1] += wg * f0.y;
                accP[2] += wg * f1.x; accP[3] += wg * f1.y;
                accP[4] += wg * f2.x; accP[5] += wg * f2.y;
                accP[6] += wg * f3.x; accP[7] += wg * f3.y;
            }
            __syncwarp();
        }
#pragma unroll
        for (int s = 16; s; s >>= 1) {
            den.x += __shfl_xor_sync(0xffffffffu, den.x, s);
            den.y += __shfl_xor_sync(0xffffffffu, den.y, s);
            den.z += __shfl_xor_sync(0xffffffffu, den.z, s);
            den.w += __shfl_xor_sync(0xffffffffu, den.w, s);
        }
        float dh = (lane < 16) ? ((lane < 8) ? den.x : den.y)
                               : ((lane < 24) ? den.z : den.w);
        if (dh > 0.f) {
            float inv = 1.f / dh;
#pragma unroll
            for (int q = 0; q < 8; q++) accT[q] += accP[q] * inv;
        }
    }
    float* ap = &g_acc[(((size_t)(m * 4 + hsel)) * NMAX + r) * 64 + 8 * (lane & 7)];
    ((float4*)ap)[0] = make_float4(accT[0], accT[1], accT[2], accT[3]);
    ((float4*)ap)[1] = make_float4(accT[4], accT[5], accT[6], accT[7]);
}

// ---------------- 4) ELU + transpose ----------------------------------------
__global__ void elu_kernel(float* __restrict__ out, int N) {
    __shared__ float t[32][33];
    int mi = blockIdx.z;
    int m = mi >> 2, i = mi & 3;
    int d0 = blockIdx.y * 32;
    int n0 = blockIdx.x * 32;
    int tx = threadIdx.x, ty = threadIdx.y;
#pragma unroll
    for (int q = 0; q < 4; q++) {
        int n = n0 + ty + q * 8;
        float v = 0.f;
        if (n < N) v = g_acc[((size_t)mi * NMAX + n) * 64 + d0 + tx];
        t[ty + q * 8][tx] = v;
    }
    __syncthreads();
#pragma unroll
    for (int q = 0; q < 4; q++) {
        int d = d0 + ty + q * 8;
        int n = n0 + tx;
        if (n < N) {
            float v = t[tx][ty + q * 8];
            out[((size_t)(m * 256 + i * 64 + d)) * N + n] = v > 0.f ? v : expm1f(v);
        }
    }
}

// ---------------- driver --------------------------------------------------
extern "C" void kernel_launch(void* const* d_in, const int* in_sizes, int n_in,
                              void* d_out, int out_size) {
    const float* x    = (const float*)d_in[0];
    const float* W    = (const float*)d_in[1];
    const float* att0 = (const float*)d_in[2];
    const float* att1 = (const float*)d_in[3];
    const int*   rows = (const int*)d_in[4];
    const int*   cols = (const int*)d_in[5];
    const float* vals = (const float*)d_in[6];
    float* out = (float*)d_out;

    int N = in_sizes[0] / D_IN;
    int E = in_sizes[4] / P_TOT;

    int nb = (N + 255) / 256;
    int eb = (E + 255) / 256;

    static cudaStream_t s_csr = nullptr;
    static cudaEvent_t ev_fork = nullptr, ev_join = nullptr;
    if (!s_csr) {
        cudaStreamCreateWithFlags(&s_csr, cudaStreamNonBlocking);
        cudaEventCreateWithFlags(&ev_fork, cudaEventDisableTiming);
        cudaEventCreateWithFlags(&ev_join, cudaEventDisableTiming);
    }

    // fork: CSR chain on s_csr, gemm on stream 0.
    // Submission order keeps gemm 4th so ncu's capture window lands on it.
    cudaEventRecord(ev_fork, 0);
    cudaStreamWaitEvent(s_csr, ev_fork, 0);

    zero_cnt_kernel<<<dim3(nb, P_TOT), 256, 0, s_csr>>>(N);          // launch 1
    hist_kernel<<<dim3(eb, P_TOT), 256, 0, s_csr>>>(rows, N, E);     // launch 2
    scanA_kernel<<<dim3(SCAN_BLOCKS, P_TOT), SCAN_CHUNK, 0, s_csr>>>(N); // launch 3
    gemm_kernel<<<dim3(8, nb), 256>>>(x, W, att0, att1, N);          // launch 4 (profiled)
    scanB_kernel<<<P_TOT, 128, 0, s_csr>>>(N);                       // launch 5
    scanC_kernel<<<dim3(SCAN_BLOCKS, P_TOT), SCAN_CHUNK, 0, s_csr>>>(N); // launch 6
    scatter_kernel<<<dim3(eb, P_TOT), 256, 0, s_csr>>>(rows, cols, vals, N, E); // 7
    cudaEventRecord(ev_join, s_csr);

    // join, then fused softmax + SpMM
    cudaStreamWaitEvent(0, ev_join, 0);
    row_agg_kernel<<<dim3((N + 7) / 8, 2), 256>>>(N);                // launch 8
    elu_kernel<<<dim3((N + 31) / 32, 2, 8), dim3(32, 8)>>>(out, N);  // launch 9
}

// round 16
// speedup vs baseline: 1.3625x; 1.3625x over previous
#include <cuda_runtime.h>
#include <cuda_fp16.h>
#include <math.h>

#define D_IN  256
#define D_OUT 64
#define NH    4
#define NMAX  100000
#define EMAX  3200000
#define P_TOT 5
#define SCAN_CHUNK 1024
#define SCAN_BLOCKS 98   // ceil(100000/1024)

// ---------------- scratch (device globals; no allocations allowed) ----------
__device__ uint4 g_hh4[(size_t)2 * NMAX * 32];                     // fp16 h, head-interleaved
__device__ __align__(16) float4 g_a0p[P_TOT * NMAX];               // a0 packed over 4 heads
__device__ __align__(16) float4 g_a1p[P_TOT * NMAX];               // a1 packed over 4 heads
__device__ __align__(16) float g_acc[(size_t)8 * NMAX * D_OUT];    // acc[mi][n][64]
__device__ int   g_cnt[P_TOT * NMAX];                              // per-row edge counts
__device__ int   g_rowptr[P_TOT * (NMAX + 1)];                     // CSR row pointers
__device__ int   g_cursor[P_TOT * NMAX];                           // scatter cursors
__device__ int   g_part[P_TOT * (SCAN_BLOCKS + 1)];                // scan partials
__device__ __align__(8) int2 g_cedge[(size_t)P_TOT * EMAX];        // CSR (col, val-bits)

// ---------------- 1) GEMM, 4-n register blocking, 2 blocks/SM ---------------
// thread t: dim-slice ds=(t>>6)*16, n-columns {nl, nl+64, nl+128, nl+192}.
// Per kk: 4 broadcast LDS.128 (W slice) reused across 4 n -> LDS:FFMA2 = 1:8.
// __launch_bounds__(256,2) keeps regs <=128 so 2 blocks/SM (R15 hit 130 regs
// -> 1 block/SM -> occupancy collapse).
__global__ void __launch_bounds__(256, 2)
gemm_kernel(const float* __restrict__ x, const float* __restrict__ W,
            const float* __restrict__ att0, const float* __restrict__ att1,
            int N) {
    __shared__ __align__(16) float Ws[64][68];
    __shared__ float att_s[3][2][64];
    __shared__ float red[4][264];         // cross-slice att reduction
    int mi  = blockIdx.x;                 // mi fast: consecutive blocks share x slice
    int m   = mi >> 2, i = mi & 3;
    int tid = threadIdx.x;
    int slice = tid >> 6, nl = tid & 63;
    int ds  = slice * 16;
    int nbase = blockIdx.y * 256;
    const float* Wb = W + (size_t)mi * D_OUT * D_IN;

    int pb = m ? 2 : 0, pc = m ? 3 : 2;
    for (int idx = tid; idx < pc * 2 * 64; idx += 256) {
        int k = idx / 128, rest = idx & 127;
        int which = rest >> 6, d = rest & 63;
        int p = pb + k;
        const float* src = which ? att1 : att0;
        att_s[k][which][d] = src[(p * NH + i) * 64 + d];
    }

    int nc[4];
#pragma unroll
    for (int j = 0; j < 4; j++) {
        int n = nbase + nl + 64 * j;
        nc[j] = n < N ? n : N - 1;        // clamp for loads
    }

    unsigned long long acc2[4][8];
#pragma unroll
    for (int j = 0; j < 4; j++)
#pragma unroll
        for (int q = 0; q < 8; q++) acc2[j][q] = 0ULL;

    for (int kc = 0; kc < 4; kc++) {
        __syncthreads();
        for (int idx = tid; idx < 4096; idx += 256) {
            int kk = idx & 63, d = idx >> 6;
            Ws[kk][d] = Wb[d * 256 + kc * 64 + kk];
        }
        __syncthreads();
        const float* xk = x + (size_t)(kc * 64) * N;
        for (int kk4 = 0; kk4 < 16; kk4++) {
            float xv[4][4];                       // [u][j], MLP=16
#pragma unroll
            for (int u = 0; u < 4; u++)
#pragma unroll
                for (int j = 0; j < 4; j++)
                    xv[u][j] = xk[(size_t)(kk4 * 4 + u) * N + nc[j]];
#pragma unroll
            for (int u = 0; u < 4; u++) {
                int kk = kk4 * 4 + u;
                const ulonglong2* wr = (const ulonglong2*)&Ws[kk][ds];
                unsigned long long w[8];
#pragma unroll
                for (int q = 0; q < 4; q++) {     // 4 x LDS.128
                    ulonglong2 t2 = wr[q];
                    w[2 * q] = t2.x; w[2 * q + 1] = t2.y;
                }
#pragma unroll
                for (int j = 0; j < 4; j++) {
                    unsigned long long xv2;
                    asm("mov.b64 %0, {%1, %1};" : "=l"(xv2) : "f"(xv[u][j]));
#pragma unroll
                    for (int q = 0; q < 8; q++)
                        asm("fma.rn.f32x2 %0, %1, %2, %0;" : "+l"(acc2[j][q]) : "l"(w[q]), "l"(xv2));
                }
            }
        }
    }

    // unpack: a[j][16]
    float a[4][16];
#pragma unroll
    for (int j = 0; j < 4; j++)
#pragma unroll
        for (int q = 0; q < 8; q++)
            asm("mov.b64 {%0, %1}, %2;" : "=f"(a[j][2 * q]), "=f"(a[j][2 * q + 1]) : "l"(acc2[j][q]));

    // fp16 h store: per n, 16 dims = 2 uint4 at slot i*8 + ds/8
#pragma unroll
    for (int j = 0; j < 4; j++) {
        int n = nbase + nl + 64 * j;
        if (n < N) {
            uint4* hq = &g_hh4[((size_t)m * NMAX + n) * 32 + i * 8 + (ds >> 3)];
            __half2 h0 = __floats2half2_rn(a[j][0],  a[j][1]);
            __half2 h1 = __floats2half2_rn(a[j][2],  a[j][3]);
            __half2 h2 = __floats2half2_rn(a[j][4],  a[j][5]);
            __half2 h3 = __floats2half2_rn(a[j][6],  a[j][7]);
            uint4 u0;
            u0.x = *(unsigned*)&h0; u0.y = *(unsigned*)&h1;
            u0.z = *(unsigned*)&h2; u0.w = *(unsigned*)&h3;
            h0 = __floats2half2_rn(a[j][8],  a[j][9]);
            h1 = __floats2half2_rn(a[j][10], a[j][11]);
            h2 = __floats2half2_rn(a[j][12], a[j][13]);
            h3 = __floats2half2_rn(a[j][14], a[j][15]);
            uint4 u1;
            u1.x = *(unsigned*)&h0; u1.y = *(unsigned*)&h1;
            u1.z = *(unsigned*)&h2; u1.w = *(unsigned*)&h3;
            hq[0] = u0; hq[1] = u1;
        }
    }

    // att scores: 16-dim partials + cross-slice smem reduction (fp32 exact)
    for (int k = 0; k < pc; k++) {
        for (int which = 0; which < 2; which++) {
            float part[4];
#pragma unroll
            for (int j = 0; j < 4; j++) {
                float s = 0.f;
#pragma unroll
                for (int d = 0; d < 16; d++)
                    s += a[j][d] * att_s[k][which][ds + d];
                part[j] = s;
            }
            __syncthreads();
#pragma unroll
            for (int j = 0; j < 4; j++)
                red[slice][nl + 64 * j] = part[j];
            __syncthreads();
            if (slice == 0) {
                int p = pb + k;
#pragma unroll
                for (int j = 0; j < 4; j++) {
                    int n_loc = nl + 64 * j;
                    int n = nbase + n_loc;
                    if (n < N) {
                        float s = red[0][n_loc] + red[1][n_loc] + red[2][n_loc] + red[3][n_loc];
                        float* dst = which ? (float*)&g_a1p[(size_t)p * NMAX + n]
                                           : (float*)&g_a0p[(size_t)p * NMAX + n];
                        dst[i] = s;
                    }
                }
            }
        }
    }
}

// ---------------- 2) CSR build ---------------------------------------------
__global__ void zero_cnt_kernel(int N) {
    int n = blockIdx.x * 256 + threadIdx.x;
    int p = blockIdx.y;
    if (n < N) g_cnt[p * NMAX + n] = 0;
}

__global__ void hist_kernel(const int* __restrict__ rows, int N, int E) {
    int e = blockIdx.x * 256 + threadIdx.x;
    int p = blockIdx.y;
    if (e >= E) return;
    int r = rows[(size_t)p * E + e];
    atomicAdd(&g_cnt[p * NMAX + r], 1);
}

// scan stage A: per-chunk totals
__global__ void scanA_kernel(int N) {
    __shared__ int wsum[32];
    int p = blockIdx.y, b = blockIdx.x, tid = threadIdx.x;
    int lane = tid & 31, wid = tid >> 5;
    int idx = b * SCAN_CHUNK + tid;
    int v = (idx < N) ? g_cnt[p * NMAX + idx] : 0;
#pragma unroll
    for (int s = 16; s; s >>= 1) v += __shfl_xor_sync(0xffffffffu, v, s);
    if (lane == 0) wsum[wid] = v;
    __syncthreads();
    if (wid == 0) {
        int t = wsum[lane];
#pragma unroll
        for (int s = 16; s; s >>= 1) t += __shfl_xor_sync(0xffffffffu, t, s);
        if (lane == 0) g_part[p * (SCAN_BLOCKS + 1) + b] = t;
    }
}

// scan stage B: exclusive scan of SCAN_BLOCKS partials per p; writes rowptr[N]
__global__ void scanB_kernel(int N) {
    __shared__ int s[128];
    int p = blockIdx.x, tid = threadIdx.x;
    int v = (tid < SCAN_BLOCKS) ? g_part[p * (SCAN_BLOCKS + 1) + tid] : 0;
    s[tid] = v;
    __syncthreads();
    for (int d = 1; d < 128; d <<= 1) {
        int t = (tid >= d) ? s[tid - d] : 0;
        __syncthreads();
        s[tid] += t;
        __syncthreads();
    }
    if (tid < SCAN_BLOCKS) g_part[p * (SCAN_BLOCKS + 1) + tid] = s[tid] - v;
    if (tid == SCAN_BLOCKS - 1) g_rowptr[p * (NMAX + 1) + N] = s[tid];
}

// scan stage C: local exclusive scan + block offset -> rowptr & cursor
__global__ void scanC_kernel(int N) {
    __shared__ int wsum[32];
    int p = blockIdx.y, b = blockIdx.x, tid = threadIdx.x;
    int lane = tid & 31, wid = tid >> 5;
    int idx = b * SCAN_CHUNK + tid;
    int v = (idx < N) ? g_cnt[p * NMAX + idx] : 0;
    int s = v;
#pragma unroll
    for (int d = 1; d < 32; d <<= 1) {
        int t = __shfl_up_sync(0xffffffffu, s, d);
        if (lane >= d) s += t;
    }
    if (lane == 31) wsum[wid] = s;
    __syncthreads();
    if (wid == 0) {
        int ws = wsum[lane];
#pragma unroll
        for (int d = 1; d < 32; d <<= 1) {
            int t = __shfl_up_sync(0xffffffffu, ws, d);
            if (lane >= d) ws += t;
        }
        wsum[lane] = ws;
    }
    __syncthreads();
    int prev = wid ? wsum[wid - 1] : 0;
    int excl = g_part[p * (SCAN_BLOCKS + 1) + b] + prev + s - v;
    if (idx < N) {
        g_rowptr[p * (NMAX + 1) + idx] = excl;
        g_cursor[p * NMAX + idx] = excl;
    }
}

__global__ void scatter_kernel(const int* __restrict__ rows, const int* __restrict__ cols,
                               const float* __restrict__ vals, int N, int E) {
    int e = blockIdx.x * 256 + threadIdx.x;
    int p = blockIdx.y;
    if (e >= E) return;
    size_t be = (size_t)p * E + e;
    int r = rows[be];
    int pos = atomicAdd(&g_cursor[p * NMAX + r], 1);
    g_cedge[(size_t)p * EMAX + pos] = make_int2(cols[be], __float_as_int(vals[be]));
}

// ---------------- 3) fused row aggregation: smem-staged edges, LDG.128 gather
__global__ void row_agg_kernel(int N) {
    __shared__ int   s_c[8][32];
    __shared__ float s_e[8][4][33];
    int lane = threadIdx.x & 31, w = threadIdx.x >> 5;
    int r = blockIdx.x * 8 + w;
    if (r >= N) return;
    int m = blockIdx.y;
    int hsel = lane >> 3;
    const uint4* hb = g_hh4 + (size_t)m * NMAX * 32;

    float accT[8];
#pragma unroll
    for (int q = 0; q < 8; q++) accT[q] = 0.f;

    int pb = m ? 2 : 0, pc = m ? 3 : 2;
    for (int k = 0; k < pc; k++) {
        int p = pb + k;
        const float4* a0 = g_a0p + (size_t)p * NMAX;
        float4 a1r = g_a1p[(size_t)p * NMAX + r];
        int start = g_rowptr[p * (NMAX + 1) + r];
        int end   = g_rowptr[p * (NMAX + 1) + r + 1];
        const int2* ced = g_cedge + (size_t)p * EMAX;

        float accP[8];
#pragma unroll
        for (int q = 0; q < 8; q++) accP[q] = 0.f;
        float4 den = make_float4(0.f, 0.f, 0.f, 0.f);

        for (int base = start; base < end; base += 32) {
            int e = base + lane;
            float e0 = 0.f, e1 = 0.f, e2 = 0.f, e3 = 0.f;
            int c = 0;
            if (e < end) {
                int2 ed = ced[e];
                c = ed.x;
                float v = __int_as_float(ed.y);
                float4 a0v = a0[c];
                e0 = __expf(v * (a0v.x + a1r.x));
                e1 = __expf(v * (a0v.y + a1r.y));
                e2 = __expf(v * (a0v.z + a1r.z));
                e3 = __expf(v * (a0v.w + a1r.w));
            }
            den.x += e0; den.y += e1; den.z += e2; den.w += e3;
            s_c[w][lane] = c;
            s_e[w][0][lane] = e0; s_e[w][1][lane] = e1;
            s_e[w][2][lane] = e2; s_e[w][3][lane] = e3;
            __syncwarp();
            int cnt = min(32, end - base);
#pragma unroll 4
            for (int j = 0; j < cnt; j++) {
                int   cj = s_c[w][j];
                float wg = s_e[w][hsel][j];
                uint4 hv = hb[(size_t)cj * 32 + lane];
                float2 f0 = __half22float2(*(__half2*)&hv.x);
                float2 f1 = __half22float2(*(__half2*)&hv.y);
                float2 f2 = __half22float2(*(__half2*)&hv.z);
                float2 f3 = __half22float2(*(__half2*)&hv.w);
                accP[0] += wg * f0.x; accP[1] += wg * f0.y;
                accP[2] += wg * f1.x; accP[3] += wg * f1.y;
                accP[4] += wg * f2.x; accP[5] += wg * f2.y;
                accP[6] += wg * f3.x; accP[7] += wg * f3.y;
            }
            __syncwarp();
        }
#pragma unroll
        for (int s = 16; s; s >>= 1) {
            den.x += __shfl_xor_sync(0xffffffffu, den.x, s);
            den.y += __shfl_xor_sync(0xffffffffu, den.y, s);
            den.z += __shfl_xor_sync(0xffffffffu, den.z, s);
            den.w += __shfl_xor_sync(0xffffffffu, den.w, s);
        }
        float dh = (lane < 16) ? ((lane < 8) ? den.x : den.y)
                               : ((lane < 24) ? den.z : den.w);
        if (dh > 0.f) {
            float inv = 1.f / dh;
#pragma unroll
            for (int q = 0; q < 8; q++) accT[q] += accP[q] * inv;
        }
    }
    float* ap = &g_acc[(((size_t)(m * 4 + hsel)) * NMAX + r) * 64 + 8 * (lane & 7)];
    ((float4*)ap)[0] = make_float4(accT[0], accT[1], accT[2], accT[3]);
    ((float4*)ap)[1] = make_float4(accT[4], accT[5], accT[6], accT[7]);
}

// ---------------- 4) ELU + transpose ----------------------------------------
__global__ void elu_kernel(float* __restrict__ out, int N) {
    __shared__ float t[32][33];
    int mi = blockIdx.z;
    int m = mi >> 2, i = mi & 3;
    int d0 = blockIdx.y * 32;
    int n0 = blockIdx.x * 32;
    int tx = threadIdx.x, ty = threadIdx.y;
#pragma unroll
    for (int q = 0; q < 4; q++) {
        int n = n0 + ty + q * 8;
        float v = 0.f;
        if (n < N) v = g_acc[((size_t)mi * NMAX + n) * 64 + d0 + tx];
        t[ty + q * 8][tx] = v;
    }
    __syncthreads();
#pragma unroll
    for (int q = 0; q < 4; q++) {
        int d = d0 + ty + q * 8;
        int n = n0 + tx;
        if (n < N) {
            float v = t[tx][ty + q * 8];
            out[((size_t)(m * 256 + i * 64 + d)) * N + n] = v > 0.f ? v : expm1f(v);
        }
    }
}

// ---------------- driver --------------------------------------------------
extern "C" void kernel_launch(void* const* d_in, const int* in_sizes, int n_in,
                              void* d_out, int out_size) {
    const float* x    = (const float*)d_in[0];
    const float* W    = (const float*)d_in[1];
    const float* att0 = (const float*)d_in[2];
    const float* att1 = (const float*)d_in[3];
    const int*   rows = (const int*)d_in[4];
    const int*   cols = (const int*)d_in[5];
    const float* vals = (const float*)d_in[6];
    float* out = (float*)d_out;

    int N = in_sizes[0] / D_IN;
    int E = in_sizes[4] / P_TOT;

    int nb = (N + 255) / 256;
    int eb = (E + 255) / 256;

    static cudaStream_t s_csr = nullptr;
    static cudaEvent_t ev_fork = nullptr, ev_join = nullptr;
    if (!s_csr) {
        cudaStreamCreateWithFlags(&s_csr, cudaStreamNonBlocking);
        cudaEventCreateWithFlags(&ev_fork, cudaEventDisableTiming);
        cudaEventCreateWithFlags(&ev_join, cudaEventDisableTiming);
    }

    // fork: CSR chain on s_csr, gemm on stream 0.
    // Submission order keeps gemm 4th so ncu's capture window lands on it.
    cudaEventRecord(ev_fork, 0);
    cudaStreamWaitEvent(s_csr, ev_fork, 0);

    zero_cnt_kernel<<<dim3(nb, P_TOT), 256, 0, s_csr>>>(N);          // launch 1
    hist_kernel<<<dim3(eb, P_TOT), 256, 0, s_csr>>>(rows, N, E);     // launch 2
    scanA_kernel<<<dim3(SCAN_BLOCKS, P_TOT), SCAN_CHUNK, 0, s_csr>>>(N); // launch 3
    gemm_kernel<<<dim3(8, nb), 256>>>(x, W, att0, att1, N);          // launch 4 (profiled)
    scanB_kernel<<<P_TOT, 128, 0, s_csr>>>(N);                       // launch 5
    scanC_kernel<<<dim3(SCAN_BLOCKS, P_TOT), SCAN_CHUNK, 0, s_csr>>>(N); // launch 6
    scatter_kernel<<<dim3(eb, P_TOT), 256, 0, s_csr>>>(rows, cols, vals, N, E); // 7
    cudaEventRecord(ev_join, s_csr);

    // join, then fused softmax + SpMM
    cudaStreamWaitEvent(0, ev_join, 0);
    row_agg_kernel<<<dim3((N + 7) / 8, 2), 256>>>(N);                // launch 8
    elu_kernel<<<dim3((N + 31) / 32, 2, 8), dim3(32, 8)>>>(out, N);  // launch 9
}